// round 14
// baseline (speedup 1.0000x reference)
#include <cuda_runtime.h>
#include <cuda_fp16.h>
#include <cstdint>

// ---------------------------------------------------------------------------
// Problem constants
// ---------------------------------------------------------------------------
#define NTOK   204800          // B*T*V = 64*128*25
#define NGRP   8192            // B*T
#define VTOK   25

// ---------------------------------------------------------------------------
// Device scratch (static; no allocation allowed)
// ---------------------------------------------------------------------------
__device__ __half g_y  [(size_t)NTOK * 256];     // LN1 out (GEMM A)
__device__ __half g_qkv[(size_t)NTOK * 768];     // QKV out
__device__ __half g_ao [(size_t)NTOK * 256];     // attention out (GEMM A)
__device__ float  g_xf [(size_t)NTOK * 256];     // residual stream (fp32)
__device__ __half g_y2 [(size_t)NTOK * 256];     // LN2 out (GEMM A)
__device__ __half g_h  [(size_t)NTOK * 1024];    // GELU out (GEMM A)
// transposed + fp16-rounded weights, stored [N][K] K-major
#define W_QKV  0
#define W_PROJ (256 * 768)
#define W_FFN1 (W_PROJ + 256 * 256)
#define W_FFN2 (W_FFN1 + 256 * 1024)
#define W_TOT  (W_FFN2 + 1024 * 256)
__device__ __half g_w[(size_t)W_TOT];

// ---------------------------------------------------------------------------
// Helpers
// ---------------------------------------------------------------------------
__device__ __forceinline__ float gelu_exact(float x) {
    return 0.5f * x * (1.0f + erff(x * 0.70710678118654752f));
}

__device__ __forceinline__ void cp16(unsigned dst, const void* src) {
    asm volatile("cp.async.cg.shared.global [%0], [%1], 16;" :: "r"(dst), "l"(src));
}
#define CP_COMMIT() asm volatile("cp.async.commit_group;")
#define CP_WAIT2()  asm volatile("cp.async.wait_group 2;" ::: "memory")
#define CP_WAIT0()  asm volatile("cp.async.wait_group 0;" ::: "memory")

// fp16 MMA m16n8k16: D(f32) += A(f16) x B(f16)
__device__ __forceinline__ void mma_f16(float* d, const unsigned* a, const unsigned* b) {
    asm volatile(
        "mma.sync.aligned.m16n8k16.row.col.f32.f16.f16.f32 "
        "{%0,%1,%2,%3}, {%4,%5,%6,%7}, {%8,%9}, {%0,%1,%2,%3};"
        : "+f"(d[0]), "+f"(d[1]), "+f"(d[2]), "+f"(d[3])
        : "r"(a[0]), "r"(a[1]), "r"(a[2]), "r"(a[3]), "r"(b[0]), "r"(b[1]));
}

__device__ __forceinline__ void ldsm_x4(unsigned* r, unsigned addr) {
    asm volatile("ldmatrix.sync.aligned.m8n8.x4.shared.b16 {%0,%1,%2,%3}, [%4];"
                 : "=r"(r[0]), "=r"(r[1]), "=r"(r[2]), "=r"(r[3]) : "r"(addr));
}

// ---------------------------------------------------------------------------
// All-weights transpose + fp16 rounding, one launch.
// blockIdx.z selects the weight; dst[n*K + k] = half(src[k*N + n]).
// ---------------------------------------------------------------------------
__global__ __launch_bounds__(256)
void transpose_all(const float* __restrict__ s0, const float* __restrict__ s1,
                   const float* __restrict__ s2, const float* __restrict__ s3,
                   __half* __restrict__ dstbase)
{
    const float* src; __half* dst; int K, N;
    switch (blockIdx.z) {
        case 0:  src = s0; dst = dstbase + W_QKV;  K = 256;  N = 768;  break;
        case 1:  src = s1; dst = dstbase + W_PROJ; K = 256;  N = 256;  break;
        case 2:  src = s2; dst = dstbase + W_FFN1; K = 256;  N = 1024; break;
        default: src = s3; dst = dstbase + W_FFN2; K = 1024; N = 256;  break;
    }
    int n0 = blockIdx.x * 32, k0 = blockIdx.y * 32;
    if (n0 >= N || k0 >= K) return;

    __shared__ float t[32][33];
    int tx = threadIdx.x & 31, ty = threadIdx.x >> 5;   // 32 x 8
    #pragma unroll
    for (int i = 0; i < 4; i++)
        t[ty + i * 8][tx] = src[(long)(k0 + ty + i * 8) * N + n0 + tx];
    __syncthreads();
    #pragma unroll
    for (int i = 0; i < 4; i++)
        dst[(long)(n0 + ty + i * 8) * K + k0 + tx] = __float2half_rn(t[tx][ty + i * 8]);
}

// ---------------------------------------------------------------------------
// LayerNorm: one warp per row of 256. Output fp16 (GEMM A operand).
// ---------------------------------------------------------------------------
__global__ __launch_bounds__(256)
void ln_kernel(const float* __restrict__ x, const float* __restrict__ g,
               const float* __restrict__ b, __half* __restrict__ y)
{
    int row  = blockIdx.x * 8 + (threadIdx.x >> 5);
    int lane = threadIdx.x & 31;
    const float* xr = x + (size_t)row * 256;

    float4 v0 = *(const float4*)(xr + lane * 4);
    float4 v1 = *(const float4*)(xr + 128 + lane * 4);

    float s = v0.x + v0.y + v0.z + v0.w + v1.x + v1.y + v1.z + v1.w;
    #pragma unroll
    for (int o = 16; o; o >>= 1) s += __shfl_xor_sync(0xFFFFFFFFu, s, o);
    float mean = s * (1.0f / 256.0f);

    float d0 = v0.x - mean, d1 = v0.y - mean, d2 = v0.z - mean, d3 = v0.w - mean;
    float d4 = v1.x - mean, d5 = v1.y - mean, d6 = v1.z - mean, d7 = v1.w - mean;
    float vs = d0*d0 + d1*d1 + d2*d2 + d3*d3 + d4*d4 + d5*d5 + d6*d6 + d7*d7;
    #pragma unroll
    for (int o = 16; o; o >>= 1) vs += __shfl_xor_sync(0xFFFFFFFFu, vs, o);
    float rstd = rsqrtf(vs * (1.0f / 256.0f) + 1e-5f);

    float4 g0 = *(const float4*)(g + lane * 4);
    float4 g1 = *(const float4*)(g + 128 + lane * 4);
    float4 b0 = *(const float4*)(b + lane * 4);
    float4 b1 = *(const float4*)(b + 128 + lane * 4);

    __half2* yr = (__half2*)(y + (size_t)row * 256);
    yr[lane * 2]          = __floats2half2_rn(d0 * rstd * g0.x + b0.x, d1 * rstd * g0.y + b0.y);
    yr[lane * 2 + 1]      = __floats2half2_rn(d2 * rstd * g0.z + b0.z, d3 * rstd * g0.w + b0.w);
    yr[64 + lane * 2]     = __floats2half2_rn(d4 * rstd * g1.x + b1.x, d5 * rstd * g1.y + b1.y);
    yr[64 + lane * 2 + 1] = __floats2half2_rn(d6 * rstd * g1.z + b1.z, d7 * rstd * g1.w + b1.w);
}

// ---------------------------------------------------------------------------
// fp16 tensor GEMM v4: C[M,N] = A[M,K](f16) @ Wt[N,K](f16)^T + epilogue
//   EPI 1: +bias -> fp16 C | EPI 2: +bias, GELU -> fp16 C
//   EPI 3: +bias+resid -> fp32 C
// CTA 128x128, 4 warps (2x2) of 64x64, mma m16n8k16 via ldmatrix.x4.
// K-chunk 32, 4-stage cp.async pipeline (wait_group 2), prefetch-before-
// compute. Pitch 20 words, conflict-free.
// ---------------------------------------------------------------------------
#define PITCH  20               // 32-bit words per tile row (16 data + 4 pad)
#define TILE_W (128 * PITCH)    // words per tile (A or B)
#define ST_W   (2 * TILE_W)     // words per stage (A+B)
#define SMEM_G (4 * ST_W * 4)   // bytes: 81920

template<int EPI>
__global__ __launch_bounds__(128, 2)
void gemm_f16(const __half* __restrict__ A, const __half* __restrict__ W,
              const float* __restrict__ bias, const float* __restrict__ resid,
              void* __restrict__ Cv, int N, int K)
{
    extern __shared__ unsigned sm[];

    int tid  = threadIdx.x;
    int w    = tid >> 5;
    int lane = tid & 31;
    int g    = lane >> 2;
    int t    = lane & 3;
    int wm   = w >> 1;      // 0..1
    int wn   = w & 1;       // 0..1

    long mBase = (long)blockIdx.y * 128;
    int  nBase = blockIdx.x * 128;

    const __half* Ab = A + mBase * (long)K;
    const __half* Wb = W + (long)nBase * K;
    unsigned smb = (unsigned)__cvta_generic_to_shared(sm);

    float acc[4][8][4];
    #pragma unroll
    for (int mt = 0; mt < 4; mt++)
        #pragma unroll
        for (int nt = 0; nt < 8; nt++)
            #pragma unroll
            for (int c = 0; c < 4; c++) acc[mt][nt][c] = 0.0f;

    int TC = K >> 5;                 // number of K=32 chunks (>= 8 always)

    #define LOAD(c)                                                        \
    {                                                                      \
        unsigned st = smb + (unsigned)((c) & 3) * (ST_W * 4u);             \
        const __half* ap = Ab + (c) * 32;                                  \
        const __half* bp = Wb + (c) * 32;                                  \
        _Pragma("unroll")                                                  \
        for (int i = 0; i < 4; i++) {                                      \
            int ch = tid + i * 128;                                        \
            int r = ch >> 2, q = ch & 3;                                   \
            unsigned so = (unsigned)((r * PITCH + q * 4) * 4);             \
            long     go = (long)r * K + q * 8;                             \
            cp16(st + so, ap + go);                                        \
            cp16(st + TILE_W * 4u + so, bp + go);                          \
        }                                                                  \
    }

    LOAD(0); CP_COMMIT();
    LOAD(1); CP_COMMIT();
    LOAD(2); CP_COMMIT();

    // ldmatrix lane addressing
    int rowA  = (lane & 7) + ((lane >> 3) & 1) * 8;   // m within 16-row tile
    int halfA = lane >> 4;                            // 16B half within k16
    int rowB  = (lane & 7) + (lane >> 4) * 8;         // n within 16-row pair
    int halfB = (lane >> 3) & 1;

    for (int c = 0; c < TC; c++) {
        CP_WAIT2();                  // chunk c landed; c+1, c+2 may be in flight
        __syncthreads();

        if (c + 3 < TC) LOAD(c + 3);
        CP_COMMIT();

        unsigned sa = smb + (unsigned)(c & 3) * (ST_W * 4u);
        unsigned sb = sa + TILE_W * 4u;

        #pragma unroll
        for (int sub = 0; sub < 2; sub++) {
            unsigned kw = (unsigned)(sub * 8);

            unsigned af[4][4];
            #pragma unroll
            for (int mt = 0; mt < 4; mt++)
                ldsm_x4(af[mt], sa + (((wm * 64 + mt * 16 + rowA) * PITCH + kw + halfA * 4) * 4));

            unsigned bf[8][2];
            #pragma unroll
            for (int p = 0; p < 4; p++) {
                unsigned r[4];
                ldsm_x4(r, sb + (((wn * 64 + p * 16 + rowB) * PITCH + kw + halfB * 4) * 4));
                bf[2*p][0] = r[0]; bf[2*p][1] = r[1];
                bf[2*p+1][0] = r[2]; bf[2*p+1][1] = r[3];
            }

            #pragma unroll
            for (int mt = 0; mt < 4; mt++)
                #pragma unroll
                for (int nt = 0; nt < 8; nt++)
                    mma_f16(acc[mt][nt], af[mt], bf[nt]);
        }
    }
    #undef LOAD

    // ---- epilogue ----
    #pragma unroll
    for (int mt = 0; mt < 4; mt++) {
        long r0 = mBase + wm * 64 + mt * 16 + g;
        long r1 = r0 + 8;
        #pragma unroll
        for (int nt = 0; nt < 8; nt++) {
            int cb = nBase + wn * 64 + nt * 8 + t * 2;
            float bb0 = bias[cb], bb1 = bias[cb + 1];
            float c0 = acc[mt][nt][0] + bb0;
            float c1 = acc[mt][nt][1] + bb1;
            float c2 = acc[mt][nt][2] + bb0;
            float c3 = acc[mt][nt][3] + bb1;
            if (EPI == 1) {          // -> fp16 output (qkv)
                __half* C = (__half*)Cv;
                *(__half2*)(C + r0 * N + cb) = __floats2half2_rn(c0, c1);
                *(__half2*)(C + r1 * N + cb) = __floats2half2_rn(c2, c3);
            } else if (EPI == 2) {   // GELU -> fp16 output
                __half* C = (__half*)Cv;
                *(__half2*)(C + r0 * N + cb) =
                    __floats2half2_rn(gelu_exact(c0), gelu_exact(c1));
                *(__half2*)(C + r1 * N + cb) =
                    __floats2half2_rn(gelu_exact(c2), gelu_exact(c3));
            } else {                 // +resid -> fp32 output
                float* C = (float*)Cv;
                float2 ra = *(const float2*)(resid + r0 * N + cb);
                float2 rb = *(const float2*)(resid + r1 * N + cb);
                float2 o0; o0.x = c0 + ra.x; o0.y = c1 + ra.y;
                float2 o1; o1.x = c2 + rb.x; o1.y = c3 + rb.y;
                *(float2*)(C + r0 * N + cb) = o0;
                *(float2*)(C + r1 * N + cb) = o1;
            }
        }
    }
}

// ---------------------------------------------------------------------------
// Cosine attention v2. One block = (group, half); 4 warps = 4 heads.
// qkv stays fp16 in smem (cp.async staged); K norms precomputed into a small
// fp32 side array and applied to logits (no re-rounding of K).
// ---------------------------------------------------------------------------
#define AQ_STRIDE 392           // halves per row: 384 data + 8 pad (784 B)

__global__ __launch_bounds__(128)
void attn_kernel(const __half* __restrict__ qkv, const float* __restrict__ ls,
                 __half* __restrict__ ao)
{
    __shared__ __half sq[VTOK * AQ_STRIDE];     // 19.6 KB
    __shared__ float  knorm[4][VTOK];

    int g    = blockIdx.x >> 1;
    int half = blockIdx.x & 1;
    int tid  = threadIdx.x;

    // stage fp16 qkv slice via cp.async: 25 rows x 48 chunks of 16B
    const __half* src = qkv + (size_t)g * VTOK * 768 + half * 128;
    unsigned smb = (unsigned)__cvta_generic_to_shared(sq);
    for (int idx = tid; idx < VTOK * 48; idx += 128) {
        int r = idx / 48, rem = idx % 48;
        int s = rem >> 4, c = rem & 15;
        cp16(smb + (unsigned)((r * AQ_STRIDE + s * 128 + c * 8) * 2),
             src + (size_t)r * 768 + s * 256 + c * 8);
    }
    CP_COMMIT();
    CP_WAIT0();
    __syncthreads();

    int w    = tid >> 5;
    int lane = tid & 31;
    int h    = half * 4 + w;

    float scale = __expf(fminf(ls[h], 4.60517018598809f));   // log(100)

    // K norms: lane j computes 1/||k_j|| (fp32 accumulation over fp16 values)
    if (lane < VTOK) {
        const uint4* kr = (const uint4*)(sq + lane * AQ_STRIDE + 128 + w * 32);
        float ss = 0.0f;
        #pragma unroll
        for (int c = 0; c < 4; c++) {
            uint4 u = kr[c];
            float2 f0 = __half22float2(*(__half2*)&u.x);
            float2 f1 = __half22float2(*(__half2*)&u.y);
            float2 f2 = __half22float2(*(__half2*)&u.z);
            float2 f3 = __half22float2(*(__half2*)&u.w);
            ss += f0.x*f0.x + f0.y*f0.y + f1.x*f1.x + f1.y*f1.y
                + f2.x*f2.x + f2.y*f2.y + f3.x*f3.x + f3.y*f3.y;
        }
        knorm[w][lane] = 1.0f / fmaxf(sqrtf(ss), 1e-12f);
    }
    __syncwarp();

    // load + normalize q row (lane i); fold cosine scale + 1/sqrt(hd)
    int i = lane < VTOK ? lane : 0;
    float q[32];
    float ss = 0.0f;
    {
        const uint4* qr = (const uint4*)(sq + i * AQ_STRIDE + w * 32);
        #pragma unroll
        for (int c = 0; c < 4; c++) {
            uint4 u = qr[c];
            float2 f0 = __half22float2(*(__half2*)&u.x);
            float2 f1 = __half22float2(*(__half2*)&u.y);
            float2 f2 = __half22float2(*(__half2*)&u.z);
            float2 f3 = __half22float2(*(__half2*)&u.w);
            q[c*8+0] = f0.x; q[c*8+1] = f0.y; q[c*8+2] = f1.x; q[c*8+3] = f1.y;
            q[c*8+4] = f2.x; q[c*8+5] = f2.y; q[c*8+6] = f3.x; q[c*8+7] = f3.y;
            ss += f0.x*f0.x + f0.y*f0.y + f1.x*f1.x + f1.y*f1.y
                + f2.x*f2.x + f2.y*f2.y + f3.x*f3.x + f3.y*f3.y;
        }
    }
    float qf = scale / (5.65685424949238f * fmaxf(sqrtf(ss), 1e-12f));
    #pragma unroll
    for (int d = 0; d < 32; d++) q[d] *= qf;

    // logits
    float p[VTOK];
    #pragma unroll
    for (int j = 0; j < VTOK; j++) {
        const uint4* kr = (const uint4*)(sq + j * AQ_STRIDE + 128 + w * 32);  // broadcast
        float a = 0.0f;
        #pragma unroll
        for (int c = 0; c < 4; c++) {
            uint4 u = kr[c];
            float2 f0 = __half22float2(*(__half2*)&u.x);
            float2 f1 = __half22float2(*(__half2*)&u.y);
            float2 f2 = __half22float2(*(__half2*)&u.z);
            float2 f3 = __half22float2(*(__half2*)&u.w);
            a += q[c*8+0]*f0.x + q[c*8+1]*f0.y + q[c*8+2]*f1.x + q[c*8+3]*f1.y
               + q[c*8+4]*f2.x + q[c*8+5]*f2.y + q[c*8+6]*f3.x + q[c*8+7]*f3.y;
        }
        p[j] = a * knorm[w][j];
    }

    // softmax (lane-local)
    float m = p[0];
    #pragma unroll
    for (int j = 1; j < VTOK; j++) m = fmaxf(m, p[j]);
    float s = 0.0f;
    #pragma unroll
    for (int j = 0; j < VTOK; j++) { p[j] = __expf(p[j] - m); s += p[j]; }
    float invs = 1.0f / s;

    // out = P @ V
    float o[32];
    #pragma unroll
    for (int d = 0; d < 32; d++) o[d] = 0.0f;
    #pragma unroll
    for (int j = 0; j < VTOK; j++) {
        const uint4* vr = (const uint4*)(sq + j * AQ_STRIDE + 256 + w * 32);  // broadcast
        float pj = p[j] * invs;
        #pragma unroll
        for (int c = 0; c < 4; c++) {
            uint4 u = vr[c];
            float2 f0 = __half22float2(*(__half2*)&u.x);
            float2 f1 = __half22float2(*(__half2*)&u.y);
            float2 f2 = __half22float2(*(__half2*)&u.z);
            float2 f3 = __half22float2(*(__half2*)&u.w);
            o[c*8+0] += pj * f0.x; o[c*8+1] += pj * f0.y;
            o[c*8+2] += pj * f1.x; o[c*8+3] += pj * f1.y;
            o[c*8+4] += pj * f2.x; o[c*8+5] += pj * f2.y;
            o[c*8+6] += pj * f3.x; o[c*8+7] += pj * f3.y;
        }
    }

    if (lane < VTOK) {
        __half2* dst = (__half2*)(ao + ((size_t)g * VTOK + lane) * 256 + h * 32);
        #pragma unroll
        for (int c = 0; c < 8; c++) {
            dst[c * 2]     = __floats2half2_rn(o[c*4+0], o[c*4+1]);
            dst[c * 2 + 1] = __floats2half2_rn(o[c*4+2], o[c*4+3]);
        }
    }
}

// ---------------------------------------------------------------------------
// Launch
// ---------------------------------------------------------------------------
extern "C" void kernel_launch(void* const* d_in, const int* in_sizes, int n_in,
                              void* d_out, int out_size)
{
    const float* x       = (const float*)d_in[0];
    const float* ln1_g   = (const float*)d_in[1];
    const float* ln1_b   = (const float*)d_in[2];
    const float* qkv_w   = (const float*)d_in[3];
    const float* qkv_b   = (const float*)d_in[4];
    const float* proj_w  = (const float*)d_in[5];
    const float* proj_b  = (const float*)d_in[6];
    const float* lscale  = (const float*)d_in[7];
    const float* ln2_g   = (const float*)d_in[8];
    const float* ln2_b   = (const float*)d_in[9];
    const float* ffn_w1  = (const float*)d_in[10];
    const float* ffn_b1  = (const float*)d_in[11];
    const float* ffn_w2  = (const float*)d_in[12];
    const float* ffn_b2  = (const float*)d_in[13];

    __half *y, *qkv, *ao, *y2, *h, *wbuf;
    float  *xf;
    cudaGetSymbolAddress((void**)&y,    g_y);
    cudaGetSymbolAddress((void**)&qkv,  g_qkv);
    cudaGetSymbolAddress((void**)&ao,   g_ao);
    cudaGetSymbolAddress((void**)&xf,   g_xf);
    cudaGetSymbolAddress((void**)&y2,   g_y2);
    cudaGetSymbolAddress((void**)&h,    g_h);
    cudaGetSymbolAddress((void**)&wbuf, g_w);

    cudaFuncSetAttribute(gemm_f16<1>, cudaFuncAttributeMaxDynamicSharedMemorySize, SMEM_G);
    cudaFuncSetAttribute(gemm_f16<2>, cudaFuncAttributeMaxDynamicSharedMemorySize, SMEM_G);
    cudaFuncSetAttribute(gemm_f16<3>, cudaFuncAttributeMaxDynamicSharedMemorySize, SMEM_G);

    // 0) all weights -> transposed [N][K] fp16, one launch
    transpose_all<<<dim3(32, 32, 4), 256>>>(qkv_w, proj_w, ffn_w1, ffn_w2, wbuf);

    // 1) LN1 -> fp16 y
    ln_kernel<<<NTOK / 8, 256>>>(x, ln1_g, ln1_b, y);
    // 2) QKV = y @ Wqkv + b  -> fp16 qkv
    gemm_f16<1><<<dim3(6, NTOK / 128), 128, SMEM_G>>>(y, wbuf + W_QKV, qkv_b, nullptr, qkv, 768, 256);
    // 3) cosine attention -> fp16 ao
    attn_kernel<<<NGRP * 2, 128>>>(qkv, lscale, ao);
    // 4) xf = ao @ Wproj + b + x  -> fp32
    gemm_f16<3><<<dim3(2, NTOK / 128), 128, SMEM_G>>>(ao, wbuf + W_PROJ, proj_b, x, xf, 256, 256);
    // 5) LN2 -> fp16 y2
    ln_kernel<<<NTOK / 8, 256>>>(xf, ln2_g, ln2_b, y2);
    // 6) h = gelu(y2 @ W1 + b1) -> fp16
    gemm_f16<2><<<dim3(8, NTOK / 128), 128, SMEM_G>>>(y2, wbuf + W_FFN1, ffn_b1, nullptr, h, 1024, 256);
    // 7) out = h @ W2 + b2 + xf -> fp32 d_out
    gemm_f16<3><<<dim3(2, NTOK / 128), 128, SMEM_G>>>(h, wbuf + W_FFN2, ffn_b2, xf, (float*)d_out, 256, 1024);
}

// round 16
// speedup vs baseline: 1.2219x; 1.2219x over previous
#include <cuda_runtime.h>
#include <cuda_fp16.h>
#include <cstdint>

// ---------------------------------------------------------------------------
// Problem constants
// ---------------------------------------------------------------------------
#define NTOK   204800          // B*T*V = 64*128*25
#define NGRP   8192            // B*T
#define VTOK   25

// ---------------------------------------------------------------------------
// Device scratch (static; no allocation allowed)
// ---------------------------------------------------------------------------
__device__ __half g_y  [(size_t)NTOK * 256];     // LN1 out (GEMM A)
__device__ __half g_qkv[(size_t)NTOK * 768];     // QKV out
__device__ __half g_ao [(size_t)NTOK * 256];     // attention out (GEMM A)
__device__ float  g_xf [(size_t)NTOK * 256];     // residual stream (fp32)
__device__ __half g_y2 [(size_t)NTOK * 256];     // LN2 out (GEMM A)
__device__ __half g_h  [(size_t)NTOK * 1024];    // GELU out (GEMM A)
// transposed + fp16-rounded weights, stored [N][K] K-major
#define W_QKV  0
#define W_PROJ (256 * 768)
#define W_FFN1 (W_PROJ + 256 * 256)
#define W_FFN2 (W_FFN1 + 256 * 1024)
#define W_TOT  (W_FFN2 + 1024 * 256)
__device__ __half g_w[(size_t)W_TOT];

// ---------------------------------------------------------------------------
// Helpers
// ---------------------------------------------------------------------------
__device__ __forceinline__ float gelu_exact(float x) {
    return 0.5f * x * (1.0f + erff(x * 0.70710678118654752f));
}

__device__ __forceinline__ void cp16(unsigned dst, const void* src) {
    asm volatile("cp.async.cg.shared.global [%0], [%1], 16;" :: "r"(dst), "l"(src));
}
#define CP_COMMIT() asm volatile("cp.async.commit_group;")
#define CP_WAIT2()  asm volatile("cp.async.wait_group 2;" ::: "memory")
#define CP_WAIT0()  asm volatile("cp.async.wait_group 0;" ::: "memory")

// fp16 MMA m16n8k16: D(f32) += A(f16) x B(f16)
__device__ __forceinline__ void mma_f16(float* d, const unsigned* a, const unsigned* b) {
    asm volatile(
        "mma.sync.aligned.m16n8k16.row.col.f32.f16.f16.f32 "
        "{%0,%1,%2,%3}, {%4,%5,%6,%7}, {%8,%9}, {%0,%1,%2,%3};"
        : "+f"(d[0]), "+f"(d[1]), "+f"(d[2]), "+f"(d[3])
        : "r"(a[0]), "r"(a[1]), "r"(a[2]), "r"(a[3]), "r"(b[0]), "r"(b[1]));
}

__device__ __forceinline__ void ldsm_x4(unsigned* r, unsigned addr) {
    asm volatile("ldmatrix.sync.aligned.m8n8.x4.shared.b16 {%0,%1,%2,%3}, [%4];"
                 : "=r"(r[0]), "=r"(r[1]), "=r"(r[2]), "=r"(r[3]) : "r"(addr));
}

__device__ __forceinline__ void ldsm_x4_t(unsigned* r, unsigned addr) {
    asm volatile("ldmatrix.sync.aligned.m8n8.x4.trans.shared.b16 {%0,%1,%2,%3}, [%4];"
                 : "=r"(r[0]), "=r"(r[1]), "=r"(r[2]), "=r"(r[3]) : "r"(addr));
}

__device__ __forceinline__ unsigned pack_h2(float a, float b) {
    __half2 h = __floats2half2_rn(a, b);
    return *reinterpret_cast<unsigned*>(&h);
}

// ---------------------------------------------------------------------------
// All-weights transpose + fp16 rounding, one launch.
// ---------------------------------------------------------------------------
__global__ __launch_bounds__(256)
void transpose_all(const float* __restrict__ s0, const float* __restrict__ s1,
                   const float* __restrict__ s2, const float* __restrict__ s3,
                   __half* __restrict__ dstbase)
{
    const float* src; __half* dst; int K, N;
    switch (blockIdx.z) {
        case 0:  src = s0; dst = dstbase + W_QKV;  K = 256;  N = 768;  break;
        case 1:  src = s1; dst = dstbase + W_PROJ; K = 256;  N = 256;  break;
        case 2:  src = s2; dst = dstbase + W_FFN1; K = 256;  N = 1024; break;
        default: src = s3; dst = dstbase + W_FFN2; K = 1024; N = 256;  break;
    }
    int n0 = blockIdx.x * 32, k0 = blockIdx.y * 32;
    if (n0 >= N || k0 >= K) return;

    __shared__ float t[32][33];
    int tx = threadIdx.x & 31, ty = threadIdx.x >> 5;   // 32 x 8
    #pragma unroll
    for (int i = 0; i < 4; i++)
        t[ty + i * 8][tx] = src[(long)(k0 + ty + i * 8) * N + n0 + tx];
    __syncthreads();
    #pragma unroll
    for (int i = 0; i < 4; i++)
        dst[(long)(n0 + ty + i * 8) * K + k0 + tx] = __float2half_rn(t[tx][ty + i * 8]);
}

// ---------------------------------------------------------------------------
// LayerNorm: one warp per row of 256. Output fp16 (GEMM A operand).
// ---------------------------------------------------------------------------
__global__ __launch_bounds__(256)
void ln_kernel(const float* __restrict__ x, const float* __restrict__ g,
               const float* __restrict__ b, __half* __restrict__ y)
{
    int row  = blockIdx.x * 8 + (threadIdx.x >> 5);
    int lane = threadIdx.x & 31;
    const float* xr = x + (size_t)row * 256;

    float4 v0 = *(const float4*)(xr + lane * 4);
    float4 v1 = *(const float4*)(xr + 128 + lane * 4);

    float s = v0.x + v0.y + v0.z + v0.w + v1.x + v1.y + v1.z + v1.w;
    #pragma unroll
    for (int o = 16; o; o >>= 1) s += __shfl_xor_sync(0xFFFFFFFFu, s, o);
    float mean = s * (1.0f / 256.0f);

    float d0 = v0.x - mean, d1 = v0.y - mean, d2 = v0.z - mean, d3 = v0.w - mean;
    float d4 = v1.x - mean, d5 = v1.y - mean, d6 = v1.z - mean, d7 = v1.w - mean;
    float vs = d0*d0 + d1*d1 + d2*d2 + d3*d3 + d4*d4 + d5*d5 + d6*d6 + d7*d7;
    #pragma unroll
    for (int o = 16; o; o >>= 1) vs += __shfl_xor_sync(0xFFFFFFFFu, vs, o);
    float rstd = rsqrtf(vs * (1.0f / 256.0f) + 1e-5f);

    float4 g0 = *(const float4*)(g + lane * 4);
    float4 g1 = *(const float4*)(g + 128 + lane * 4);
    float4 b0 = *(const float4*)(b + lane * 4);
    float4 b1 = *(const float4*)(b + 128 + lane * 4);

    __half2* yr = (__half2*)(y + (size_t)row * 256);
    yr[lane * 2]          = __floats2half2_rn(d0 * rstd * g0.x + b0.x, d1 * rstd * g0.y + b0.y);
    yr[lane * 2 + 1]      = __floats2half2_rn(d2 * rstd * g0.z + b0.z, d3 * rstd * g0.w + b0.w);
    yr[64 + lane * 2]     = __floats2half2_rn(d4 * rstd * g1.x + b1.x, d5 * rstd * g1.y + b1.y);
    yr[64 + lane * 2 + 1] = __floats2half2_rn(d6 * rstd * g1.z + b1.z, d7 * rstd * g1.w + b1.w);
}

// ---------------------------------------------------------------------------
// fp16 tensor GEMM v4 (unchanged from R13 measured state)
// ---------------------------------------------------------------------------
#define PITCH  20
#define TILE_W (128 * PITCH)
#define ST_W   (2 * TILE_W)
#define SMEM_G (4 * ST_W * 4)   // 81920 B

template<int EPI>
__global__ __launch_bounds__(128, 2)
void gemm_f16(const __half* __restrict__ A, const __half* __restrict__ W,
              const float* __restrict__ bias, const float* __restrict__ resid,
              void* __restrict__ Cv, int N, int K)
{
    extern __shared__ unsigned sm[];

    int tid  = threadIdx.x;
    int w    = tid >> 5;
    int lane = tid & 31;
    int g    = lane >> 2;
    int t    = lane & 3;
    int wm   = w >> 1;
    int wn   = w & 1;

    long mBase = (long)blockIdx.y * 128;
    int  nBase = blockIdx.x * 128;

    const __half* Ab = A + mBase * (long)K;
    const __half* Wb = W + (long)nBase * K;
    unsigned smb = (unsigned)__cvta_generic_to_shared(sm);

    float acc[4][8][4];
    #pragma unroll
    for (int mt = 0; mt < 4; mt++)
        #pragma unroll
        for (int nt = 0; nt < 8; nt++)
            #pragma unroll
            for (int c = 0; c < 4; c++) acc[mt][nt][c] = 0.0f;

    int TC = K >> 5;

    #define LOAD(c)                                                        \
    {                                                                      \
        unsigned st = smb + (unsigned)((c) & 3) * (ST_W * 4u);             \
        const __half* ap = Ab + (c) * 32;                                  \
        const __half* bp = Wb + (c) * 32;                                  \
        _Pragma("unroll")                                                  \
        for (int i = 0; i < 4; i++) {                                      \
            int ch = tid + i * 128;                                        \
            int r = ch >> 2, q = ch & 3;                                   \
            unsigned so = (unsigned)((r * PITCH + q * 4) * 4);             \
            long     go = (long)r * K + q * 8;                             \
            cp16(st + so, ap + go);                                        \
            cp16(st + TILE_W * 4u + so, bp + go);                          \
        }                                                                  \
    }

    LOAD(0); CP_COMMIT();
    LOAD(1); CP_COMMIT();
    LOAD(2); CP_COMMIT();

    int rowA  = (lane & 7) + ((lane >> 3) & 1) * 8;
    int halfA = lane >> 4;
    int rowB  = (lane & 7) + (lane >> 4) * 8;
    int halfB = (lane >> 3) & 1;

    for (int c = 0; c < TC; c++) {
        CP_WAIT2();
        __syncthreads();

        if (c + 3 < TC) LOAD(c + 3);
        CP_COMMIT();

        unsigned sa = smb + (unsigned)(c & 3) * (ST_W * 4u);
        unsigned sb = sa + TILE_W * 4u;

        #pragma unroll
        for (int sub = 0; sub < 2; sub++) {
            unsigned kw = (unsigned)(sub * 8);

            unsigned af[4][4];
            #pragma unroll
            for (int mt = 0; mt < 4; mt++)
                ldsm_x4(af[mt], sa + (((wm * 64 + mt * 16 + rowA) * PITCH + kw + halfA * 4) * 4));

            unsigned bf[8][2];
            #pragma unroll
            for (int p = 0; p < 4; p++) {
                unsigned r[4];
                ldsm_x4(r, sb + (((wn * 64 + p * 16 + rowB) * PITCH + kw + halfB * 4) * 4));
                bf[2*p][0] = r[0]; bf[2*p][1] = r[1];
                bf[2*p+1][0] = r[2]; bf[2*p+1][1] = r[3];
            }

            #pragma unroll
            for (int mt = 0; mt < 4; mt++)
                #pragma unroll
                for (int nt = 0; nt < 8; nt++)
                    mma_f16(acc[mt][nt], af[mt], bf[nt]);
        }
    }
    #undef LOAD

    #pragma unroll
    for (int mt = 0; mt < 4; mt++) {
        long r0 = mBase + wm * 64 + mt * 16 + g;
        long r1 = r0 + 8;
        #pragma unroll
        for (int nt = 0; nt < 8; nt++) {
            int cb = nBase + wn * 64 + nt * 8 + t * 2;
            float bb0 = bias[cb], bb1 = bias[cb + 1];
            float c0 = acc[mt][nt][0] + bb0;
            float c1 = acc[mt][nt][1] + bb1;
            float c2 = acc[mt][nt][2] + bb0;
            float c3 = acc[mt][nt][3] + bb1;
            if (EPI == 1) {
                __half* C = (__half*)Cv;
                *(__half2*)(C + r0 * N + cb) = __floats2half2_rn(c0, c1);
                *(__half2*)(C + r1 * N + cb) = __floats2half2_rn(c2, c3);
            } else if (EPI == 2) {
                __half* C = (__half*)Cv;
                *(__half2*)(C + r0 * N + cb) =
                    __floats2half2_rn(gelu_exact(c0), gelu_exact(c1));
                *(__half2*)(C + r1 * N + cb) =
                    __floats2half2_rn(gelu_exact(c2), gelu_exact(c3));
            } else {
                float* C = (float*)Cv;
                float2 ra = *(const float2*)(resid + r0 * N + cb);
                float2 rb = *(const float2*)(resid + r1 * N + cb);
                float2 o0; o0.x = c0 + ra.x; o0.y = c1 + ra.y;
                float2 o1; o1.x = c2 + rb.x; o1.y = c3 + rb.y;
                *(float2*)(C + r0 * N + cb) = o0;
                *(float2*)(C + r1 * N + cb) = o1;
            }
        }
    }
}

// ---------------------------------------------------------------------------
// Cosine attention v3 — tensor-core (mma m16n8k16), one warp per head.
// Block = (group, half). qkv fp16 in smem, rows 25..31 zero-padded.
// S = Q@K^T (fp32 acc), post-mma scaling by qf[row]*kn[col], fragment
// softmax, P->fp16 register remap, O = P@V (fp32 acc).
// ---------------------------------------------------------------------------
#define AQ_STRIDE 392           // halves per row: 384 data + 8 pad

__global__ __launch_bounds__(128)
void attn_kernel(const __half* __restrict__ qkv, const float* __restrict__ ls,
                 __half* __restrict__ ao)
{
    __shared__ __half sq[32 * AQ_STRIDE];       // 25.1 KB (32 rows incl. pads)
    __shared__ float  qn[4][32], kn[4][32];

    int grp  = blockIdx.x >> 1;
    int half = blockIdx.x & 1;
    int tid  = threadIdx.x;

    // stage fp16 qkv slice (25 rows x 48 16B-chunks) + zero pad rows 25..31
    const __half* src = qkv + (size_t)grp * VTOK * 768 + half * 128;
    unsigned smb = (unsigned)__cvta_generic_to_shared(sq);
    for (int idx = tid; idx < VTOK * 48; idx += 128) {
        int r = idx / 48, rem = idx % 48;
        int s = rem >> 4, c = rem & 15;
        cp16(smb + (unsigned)((r * AQ_STRIDE + s * 128 + c * 8) * 2),
             src + (size_t)r * 768 + s * 256 + c * 8);
    }
    for (int idx = tid; idx < 7 * 48; idx += 128) {
        int r = 25 + idx / 48, c = idx % 48;
        *(uint4*)(sq + r * AQ_STRIDE + c * 8) = make_uint4(0, 0, 0, 0);
    }
    CP_COMMIT();
    CP_WAIT0();
    __syncthreads();

    int w    = tid >> 5;
    int lane = tid & 31;
    int g    = lane >> 2;
    int t    = lane & 3;
    int h    = half * 4 + w;
    int hoff = w * 32;

    float scale = __expf(fminf(ls[h], 4.60517018598809f));   // log(100)

    // per-row scale factors
    if (lane < VTOK) {
        float ssq = 0.0f, ssk = 0.0f;
        const uint4* qr = (const uint4*)(sq + lane * AQ_STRIDE + hoff);
        const uint4* kr = (const uint4*)(sq + lane * AQ_STRIDE + 128 + hoff);
        #pragma unroll
        for (int c = 0; c < 4; c++) {
            uint4 uq = qr[c], uk = kr[c];
            #pragma unroll
            for (int u = 0; u < 4; u++) {
                float2 fq = __half22float2(*(((__half2*)&uq) + u));
                float2 fk = __half22float2(*(((__half2*)&uk) + u));
                ssq += fq.x * fq.x + fq.y * fq.y;
                ssk += fk.x * fk.x + fk.y * fk.y;
            }
        }
        qn[w][lane] = scale / (5.65685424949238f * fmaxf(sqrtf(ssq), 1e-12f));
        kn[w][lane] = 1.0f / fmaxf(sqrtf(ssk), 1e-12f);
    } else {
        qn[w][lane] = 0.0f;
        kn[w][lane] = 0.0f;
    }
    __syncwarp();

    // ---- load fragments ----
    // Q A-frags: [mt][kb] (m16 x k16 tiles)
    unsigned aq[2][2][4];
    #pragma unroll
    for (int mt = 0; mt < 2; mt++)
        #pragma unroll
        for (int kb = 0; kb < 2; kb++) {
            int row = mt * 16 + (lane & 7) + ((lane >> 3) & 1) * 8;
            int col = hoff + kb * 16 + (lane >> 4) * 8;
            ldsm_x4(aq[mt][kb], smb + (unsigned)((row * AQ_STRIDE + col) * 2));
        }
    // K B-frags: bk[kb][jt][2] (k=d dim, n=token j)
    unsigned bk[2][4][2];
    #pragma unroll
    for (int jb = 0; jb < 2; jb++)
        #pragma unroll
        for (int kb = 0; kb < 2; kb++) {
            int row = jb * 16 + (lane & 7) + (lane >> 4) * 8;
            int col = 128 + hoff + kb * 16 + ((lane >> 3) & 1) * 8;
            unsigned r[4];
            ldsm_x4(r, smb + (unsigned)((row * AQ_STRIDE + col) * 2));
            bk[kb][2*jb][0]   = r[0]; bk[kb][2*jb][1]   = r[1];
            bk[kb][2*jb+1][0] = r[2]; bk[kb][2*jb+1][1] = r[3];
        }

    // ---- S = Q @ K^T ----
    float s[2][4][4];
    #pragma unroll
    for (int mt = 0; mt < 2; mt++)
        #pragma unroll
        for (int jt = 0; jt < 4; jt++) {
            s[mt][jt][0] = s[mt][jt][1] = s[mt][jt][2] = s[mt][jt][3] = 0.0f;
            mma_f16(s[mt][jt], aq[mt][0], bk[0][jt]);
            mma_f16(s[mt][jt], aq[mt][1], bk[1][jt]);
        }

    // ---- scale + softmax on fragments ----
    float qf0[2], qf1[2];
    #pragma unroll
    for (int mt = 0; mt < 2; mt++) {
        qf0[mt] = qn[w][mt * 16 + g];
        qf1[mt] = qn[w][mt * 16 + g + 8];
    }
    float kc0[4], kc1[4];
    #pragma unroll
    for (int jt = 0; jt < 4; jt++) {
        kc0[jt] = kn[w][jt * 8 + 2 * t];
        kc1[jt] = kn[w][jt * 8 + 2 * t + 1];
    }
    #pragma unroll
    for (int mt = 0; mt < 2; mt++)
        #pragma unroll
        for (int jt = 0; jt < 4; jt++) {
            s[mt][jt][0] *= qf0[mt] * kc0[jt];
            s[mt][jt][1] *= qf0[mt] * kc1[jt];
            s[mt][jt][2] *= qf1[mt] * kc0[jt];
            s[mt][jt][3] *= qf1[mt] * kc1[jt];
        }

    // row max (4 rows per lane: (mt,lo),(mt,hi))
    float mx[2][2];
    #pragma unroll
    for (int mt = 0; mt < 2; mt++) {
        float a = s[mt][0][0], b = s[mt][0][2];
        #pragma unroll
        for (int jt = 0; jt < 4; jt++) {
            a = fmaxf(a, fmaxf(s[mt][jt][0], s[mt][jt][1]));
            b = fmaxf(b, fmaxf(s[mt][jt][2], s[mt][jt][3]));
        }
        mx[mt][0] = a; mx[mt][1] = b;
    }
    #pragma unroll
    for (int o = 1; o <= 2; o <<= 1) {
        #pragma unroll
        for (int mt = 0; mt < 2; mt++) {
            mx[mt][0] = fmaxf(mx[mt][0], __shfl_xor_sync(0xFFFFFFFFu, mx[mt][0], o));
            mx[mt][1] = fmaxf(mx[mt][1], __shfl_xor_sync(0xFFFFFFFFu, mx[mt][1], o));
        }
    }

    // exp; zero pad cols (>=25): jt=3 cols 24+2t / 25+2t
    #pragma unroll
    for (int mt = 0; mt < 2; mt++)
        #pragma unroll
        for (int jt = 0; jt < 4; jt++) {
            s[mt][jt][0] = __expf(s[mt][jt][0] - mx[mt][0]);
            s[mt][jt][1] = __expf(s[mt][jt][1] - mx[mt][0]);
            s[mt][jt][2] = __expf(s[mt][jt][2] - mx[mt][1]);
            s[mt][jt][3] = __expf(s[mt][jt][3] - mx[mt][1]);
        }
    if (t > 0) {
        #pragma unroll
        for (int mt = 0; mt < 2; mt++) { s[mt][3][0] = 0.0f; s[mt][3][2] = 0.0f; }
    }
    #pragma unroll
    for (int mt = 0; mt < 2; mt++) { s[mt][3][1] = 0.0f; s[mt][3][3] = 0.0f; }

    // row sum
    float sm2[2][2];
    #pragma unroll
    for (int mt = 0; mt < 2; mt++) {
        float a = 0.0f, b = 0.0f;
        #pragma unroll
        for (int jt = 0; jt < 4; jt++) {
            a += s[mt][jt][0] + s[mt][jt][1];
            b += s[mt][jt][2] + s[mt][jt][3];
        }
        sm2[mt][0] = a; sm2[mt][1] = b;
    }
    #pragma unroll
    for (int o = 1; o <= 2; o <<= 1) {
        #pragma unroll
        for (int mt = 0; mt < 2; mt++) {
            sm2[mt][0] += __shfl_xor_sync(0xFFFFFFFFu, sm2[mt][0], o);
            sm2[mt][1] += __shfl_xor_sync(0xFFFFFFFFu, sm2[mt][1], o);
        }
    }
    float inv[2][2];
    #pragma unroll
    for (int mt = 0; mt < 2; mt++) {
        inv[mt][0] = 1.0f / sm2[mt][0];
        inv[mt][1] = 1.0f / sm2[mt][1];
    }

    // ---- pack P (A-frags) directly from S fragments ----
    unsigned P[2][2][4];
    #pragma unroll
    for (int mt = 0; mt < 2; mt++)
        #pragma unroll
        for (int kk = 0; kk < 2; kk++) {
            P[mt][kk][0] = pack_h2(s[mt][2*kk][0]   * inv[mt][0], s[mt][2*kk][1]   * inv[mt][0]);
            P[mt][kk][1] = pack_h2(s[mt][2*kk][2]   * inv[mt][1], s[mt][2*kk][3]   * inv[mt][1]);
            P[mt][kk][2] = pack_h2(s[mt][2*kk+1][0] * inv[mt][0], s[mt][2*kk+1][1] * inv[mt][0]);
            P[mt][kk][3] = pack_h2(s[mt][2*kk+1][2] * inv[mt][1], s[mt][2*kk+1][3] * inv[mt][1]);
        }

    // ---- V B-frags via ldmatrix.trans: bv[kk][dt][2] (k=token j, n=dim d) ----
    unsigned bv[2][4][2];
    #pragma unroll
    for (int jb = 0; jb < 2; jb++)
        #pragma unroll
        for (int db = 0; db < 2; db++) {
            int row = jb * 16 + (lane & 7) + ((lane >> 3) & 1) * 8;
            int col = 256 + hoff + db * 16 + (lane >> 4) * 8;
            unsigned r[4];
            ldsm_x4_t(r, smb + (unsigned)((row * AQ_STRIDE + col) * 2));
            bv[jb][2*db][0]   = r[0]; bv[jb][2*db][1]   = r[1];
            bv[jb][2*db+1][0] = r[2]; bv[jb][2*db+1][1] = r[3];
        }

    // ---- O = P @ V ----
    float o[2][4][4];
    #pragma unroll
    for (int mt = 0; mt < 2; mt++)
        #pragma unroll
        for (int dt = 0; dt < 4; dt++) {
            o[mt][dt][0] = o[mt][dt][1] = o[mt][dt][2] = o[mt][dt][3] = 0.0f;
            mma_f16(o[mt][dt], P[mt][0], bv[0][dt]);
            mma_f16(o[mt][dt], P[mt][1], bv[1][dt]);
        }

    // ---- store (rows < 25) ----
    __half* aobase = ao + ((size_t)grp * VTOK) * 256 + h * 32;
    #pragma unroll
    for (int mt = 0; mt < 2; mt++) {
        int r0 = mt * 16 + g;
        int r1 = r0 + 8;
        #pragma unroll
        for (int dt = 0; dt < 4; dt++) {
            int col = dt * 8 + 2 * t;
            *(__half2*)(aobase + (size_t)r0 * 256 + col) =
                __floats2half2_rn(o[mt][dt][0], o[mt][dt][1]);
            if (r1 < VTOK)
                *(__half2*)(aobase + (size_t)r1 * 256 + col) =
                    __floats2half2_rn(o[mt][dt][2], o[mt][dt][3]);
        }
    }
}

// ---------------------------------------------------------------------------
// Launch
// ---------------------------------------------------------------------------
extern "C" void kernel_launch(void* const* d_in, const int* in_sizes, int n_in,
                              void* d_out, int out_size)
{
    const float* x       = (const float*)d_in[0];
    const float* ln1_g   = (const float*)d_in[1];
    const float* ln1_b   = (const float*)d_in[2];
    const float* qkv_w   = (const float*)d_in[3];
    const float* qkv_b   = (const float*)d_in[4];
    const float* proj_w  = (const float*)d_in[5];
    const float* proj_b  = (const float*)d_in[6];
    const float* lscale  = (const float*)d_in[7];
    const float* ln2_g   = (const float*)d_in[8];
    const float* ln2_b   = (const float*)d_in[9];
    const float* ffn_w1  = (const float*)d_in[10];
    const float* ffn_b1  = (const float*)d_in[11];
    const float* ffn_w2  = (const float*)d_in[12];
    const float* ffn_b2  = (const float*)d_in[13];

    __half *y, *qkv, *ao, *y2, *h, *wbuf;
    float  *xf;
    cudaGetSymbolAddress((void**)&y,    g_y);
    cudaGetSymbolAddress((void**)&qkv,  g_qkv);
    cudaGetSymbolAddress((void**)&ao,   g_ao);
    cudaGetSymbolAddress((void**)&xf,   g_xf);
    cudaGetSymbolAddress((void**)&y2,   g_y2);
    cudaGetSymbolAddress((void**)&h,    g_h);
    cudaGetSymbolAddress((void**)&wbuf, g_w);

    cudaFuncSetAttribute(gemm_f16<1>, cudaFuncAttributeMaxDynamicSharedMemorySize, SMEM_G);
    cudaFuncSetAttribute(gemm_f16<2>, cudaFuncAttributeMaxDynamicSharedMemorySize, SMEM_G);
    cudaFuncSetAttribute(gemm_f16<3>, cudaFuncAttributeMaxDynamicSharedMemorySize, SMEM_G);

    // 0) all weights -> transposed [N][K] fp16, one launch
    transpose_all<<<dim3(32, 32, 4), 256>>>(qkv_w, proj_w, ffn_w1, ffn_w2, wbuf);

    // 1) LN1 -> fp16 y
    ln_kernel<<<NTOK / 8, 256>>>(x, ln1_g, ln1_b, y);
    // 2) QKV = y @ Wqkv + b  -> fp16 qkv
    gemm_f16<1><<<dim3(6, NTOK / 128), 128, SMEM_G>>>(y, wbuf + W_QKV, qkv_b, nullptr, qkv, 768, 256);
    // 3) cosine attention (tensor-core) -> fp16 ao
    attn_kernel<<<NGRP * 2, 128>>>(qkv, lscale, ao);
    // 4) xf = ao @ Wproj + b + x  -> fp32
    gemm_f16<3><<<dim3(2, NTOK / 128), 128, SMEM_G>>>(ao, wbuf + W_PROJ, proj_b, x, xf, 256, 256);
    // 5) LN2 -> fp16 y2
    ln_kernel<<<NTOK / 8, 256>>>(xf, ln2_g, ln2_b, y2);
    // 6) h = gelu(y2 @ W1 + b1) -> fp16
    gemm_f16<2><<<dim3(8, NTOK / 128), 128, SMEM_G>>>(y2, wbuf + W_FFN1, ffn_b1, nullptr, h, 1024, 256);
    // 7) out = h @ W2 + b2 + xf -> fp32 d_out
    gemm_f16<3><<<dim3(2, NTOK / 128), 128, SMEM_G>>>(h, wbuf + W_FFN2, ffn_b2, xf, (float*)d_out, 256, 1024);
}